// round 3
// baseline (speedup 1.0000x reference)
#include <cuda_runtime.h>
#include <cuda_fp16.h>
#include <cuda_bf16.h>
#include <mma.h>
#include <math.h>

using namespace nvcuda;

#define B_  2
#define T_  2048
#define C_  1024
#define H_  16
#define HD  64
#define M_TOTAL (B_ * T_)          // 4096
#define N3C (3 * C_)               // 3072
#define SLAB ((size_t)T_ * HD)

// fp16-normalized copies of the inputs
__device__ __half g_x[M_TOTAL * C_];
__device__ __half g_W[C_ * N3C];
__device__ __half g_b[N3C];
// q/k/v in [B][H][T][HD] fp16 layout
__device__ __half g_q[B_ * H_ * T_ * HD];
__device__ __half g_k[B_ * H_ * T_ * HD];
__device__ __half g_v[B_ * H_ * T_ * HD];
// detected input dtype: 0=fp16, 1=bf16, 2=fp32
__device__ int g_flag;

// ---------------------------------------------------------------------------
// Probe: decide how to interpret the raw input bytes. x ~ N(0,1), E|x|=0.798.
// Score each interpretation by |log(mean|v| / 0.798)|; pick argmin.
// ---------------------------------------------------------------------------
__global__ void probe_kernel(const void* xraw) {
    __shared__ float s[3];
    const int tid = threadIdx.x;
    if (tid < 3) s[tid] = 0.0f;
    __syncthreads();

    const __half*         ph = (const __half*)xraw;
    const __nv_bfloat16*  pb = (const __nv_bfloat16*)xraw;
    const float*          pf = (const float*)xraw;

    float a0 = 0.f, a1 = 0.f, a2 = 0.f;
    for (int i = tid; i < 4096; i += 256) {
        float v0 = fabsf(__half2float(ph[i]));
        float v1 = fabsf(__bfloat162float(pb[i]));
        float v2 = fabsf(pf[i]);
        if (!isfinite(v0) || v0 > 1e6f) v0 = 1e6f;
        if (!isfinite(v1) || v1 > 1e6f) v1 = 1e6f;
        if (!isfinite(v2) || v2 > 1e6f) v2 = 1e6f;
        a0 += v0; a1 += v1; a2 += v2;
    }
    atomicAdd(&s[0], a0);
    atomicAdd(&s[1], a1);
    atomicAdd(&s[2], a2);
    __syncthreads();

    if (tid == 0) {
        int best = 0;
        float bestd = 1e30f;
        #pragma unroll
        for (int j = 0; j < 3; j++) {
            float m = fmaxf(s[j] / 4096.0f, 1e-30f);
            float d = fabsf(logf(m / 0.798f));
            if (d < bestd) { bestd = d; best = j; }
        }
        g_flag = best;
    }
}

// ---------------------------------------------------------------------------
// Convert a raw input buffer into fp16 scratch using the detected dtype.
// ---------------------------------------------------------------------------
__global__ void conv_kernel(const void* __restrict__ src,
                            __half* __restrict__ dst, int n) {
    const int flag = g_flag;
    const int stride = gridDim.x * blockDim.x;
    for (int i = blockIdx.x * blockDim.x + threadIdx.x; i < n; i += stride) {
        float v;
        if (flag == 0)      v = __half2float(((const __half*)src)[i]);
        else if (flag == 1) v = __bfloat162float(((const __nv_bfloat16*)src)[i]);
        else                v = ((const float*)src)[i];
        dst[i] = __float2half(v);
    }
}

// ---------------------------------------------------------------------------
// Kernel 1: QKV = x @ W + b -> scatter into q/k/v [B][H][T][HD]
// ---------------------------------------------------------------------------
__global__ void qkv_kernel() {
    __shared__ __half As[64 * 72];
    __shared__ __half Bs[64 * 72];
    __shared__ float  Cs[64 * 72];

    const int tm  = blockIdx.x;
    const int tn  = blockIdx.y;
    const int tid = threadIdx.x;
    const int warp = tid >> 5;
    const int wr = warp >> 1, wc = warp & 1;

    wmma::fragment<wmma::accumulator, 16, 16, 16, float> acc[2][2];
    #pragma unroll
    for (int i = 0; i < 2; i++)
        #pragma unroll
        for (int j = 0; j < 2; j++)
            wmma::fill_fragment(acc[i][j], 0.0f);

    for (int k0 = 0; k0 < C_; k0 += 64) {
        #pragma unroll
        for (int v = tid; v < 512; v += 128) {
            int r = v >> 3, c8 = (v & 7) << 3;
            *(uint4*)&As[r * 72 + c8] =
                *(const uint4*)&g_x[(size_t)(tm * 64 + r) * C_ + k0 + c8];
            *(uint4*)&Bs[r * 72 + c8] =
                *(const uint4*)&g_W[(size_t)(k0 + r) * N3C + tn * 64 + c8];
        }
        __syncthreads();

        #pragma unroll
        for (int kk = 0; kk < 64; kk += 16) {
            wmma::fragment<wmma::matrix_a, 16, 16, 16, __half, wmma::row_major> af[2];
            wmma::fragment<wmma::matrix_b, 16, 16, 16, __half, wmma::row_major> bf[2];
            #pragma unroll
            for (int i = 0; i < 2; i++)
                wmma::load_matrix_sync(af[i], &As[(wr * 32 + i * 16) * 72 + kk], 72);
            #pragma unroll
            for (int j = 0; j < 2; j++)
                wmma::load_matrix_sync(bf[j], &Bs[kk * 72 + wc * 32 + j * 16], 72);
            #pragma unroll
            for (int i = 0; i < 2; i++)
                #pragma unroll
                for (int j = 0; j < 2; j++)
                    wmma::mma_sync(acc[i][j], af[i], bf[j], acc[i][j]);
        }
        __syncthreads();
    }

    #pragma unroll
    for (int i = 0; i < 2; i++)
        #pragma unroll
        for (int j = 0; j < 2; j++)
            wmma::store_matrix_sync(&Cs[(wr * 32 + i * 16) * 72 + wc * 32 + j * 16],
                                    acc[i][j], 72, wmma::mem_row_major);
    __syncthreads();

    const int third = tn >> 4;          // 0=q 1=k 2=v
    const int h     = tn & 15;
    __half* dst = (third == 0) ? g_q : (third == 1) ? g_k : g_v;

    #pragma unroll
    for (int e = tid; e < 4096; e += 128) {
        int r = e >> 6, c = e & 63;
        int row = tm * 64 + r;
        int b = row >> 11;
        int t = row & 2047;
        float val = Cs[r * 72 + c] + __half2float(g_b[tn * 64 + c]);
        dst[(((size_t)(b * H_ + h)) * T_ + t) * HD + c] = __float2half(val);
    }
}

// ---------------------------------------------------------------------------
// Kernel 2: causal ReLU attention (flash-style, causal tile skip)
// ---------------------------------------------------------------------------
__global__ void attn_kernel(float* __restrict__ out) {
    __shared__ __half Qs[64 * 72];
    __shared__ __half KPs[64 * 72];
    __shared__ __half Vs[64 * 72];
    __shared__ float  Ss[64 * 72];

    const int qi = blockIdx.x;
    const int h  = blockIdx.y;
    const int b  = blockIdx.z;
    const int tid = threadIdx.x;
    const int warp = tid >> 5;
    const int wr = warp >> 1, wc = warp & 1;

    const size_t slab = ((size_t)(b * H_ + h)) * SLAB;
    const __half* qbase = g_q + slab + (size_t)qi * 64 * HD;
    const __half* kbase = g_k + slab;
    const __half* vbase = g_v + slab;

    #pragma unroll
    for (int v = tid; v < 512; v += 128) {
        int r = v >> 3, c8 = (v & 7) << 3;
        *(uint4*)&Qs[r * 72 + c8] = *(const uint4*)&qbase[r * 64 + c8];
    }

    wmma::fragment<wmma::accumulator, 16, 16, 16, float> accy[2][2];
    #pragma unroll
    for (int i = 0; i < 2; i++)
        #pragma unroll
        for (int j = 0; j < 2; j++)
            wmma::fill_fragment(accy[i][j], 0.0f);

    const float scale = 0.125f;
    const int qglob0 = qi * 64;

    for (int j = 0; j <= qi; j++) {
        #pragma unroll
        for (int v = tid; v < 512; v += 128) {
            int r = v >> 3, c8 = (v & 7) << 3;
            *(uint4*)&KPs[r * 72 + c8] =
                *(const uint4*)&kbase[(size_t)(j * 64 + r) * HD + c8];
            *(uint4*)&Vs[r * 72 + c8] =
                *(const uint4*)&vbase[(size_t)(j * 64 + r) * HD + c8];
        }
        __syncthreads();

        wmma::fragment<wmma::accumulator, 16, 16, 16, float> accs[2][2];
        #pragma unroll
        for (int i = 0; i < 2; i++)
            #pragma unroll
            for (int jj = 0; jj < 2; jj++)
                wmma::fill_fragment(accs[i][jj], 0.0f);

        #pragma unroll
        for (int kk = 0; kk < 64; kk += 16) {
            wmma::fragment<wmma::matrix_a, 16, 16, 16, __half, wmma::row_major> af[2];
            wmma::fragment<wmma::matrix_b, 16, 16, 16, __half, wmma::col_major> bf[2];
            #pragma unroll
            for (int i = 0; i < 2; i++)
                wmma::load_matrix_sync(af[i], &Qs[(wr * 32 + i * 16) * 72 + kk], 72);
            #pragma unroll
            for (int jj = 0; jj < 2; jj++)
                wmma::load_matrix_sync(bf[jj], &KPs[(wc * 32 + jj * 16) * 72 + kk], 72);
            #pragma unroll
            for (int i = 0; i < 2; i++)
                #pragma unroll
                for (int jj = 0; jj < 2; jj++)
                    wmma::mma_sync(accs[i][jj], af[i], bf[jj], accs[i][jj]);
        }
        #pragma unroll
        for (int i = 0; i < 2; i++)
            #pragma unroll
            for (int jj = 0; jj < 2; jj++)
                wmma::store_matrix_sync(&Ss[(wr * 32 + i * 16) * 72 + wc * 32 + jj * 16],
                                        accs[i][jj], 72, wmma::mem_row_major);
        __syncthreads();

        const int kglob0 = j * 64;
        #pragma unroll
        for (int e = tid; e < 4096; e += 128) {
            int r = e >> 6, c = e & 63;
            float s = Ss[r * 72 + c] * scale;
            s = fmaxf(s, 0.0f);
            if (kglob0 + c > qglob0 + r) s = 0.0f;
            KPs[r * 72 + c] = __float2half(s);
        }
        __syncthreads();

        #pragma unroll
        for (int kk = 0; kk < 64; kk += 16) {
            wmma::fragment<wmma::matrix_a, 16, 16, 16, __half, wmma::row_major> af[2];
            wmma::fragment<wmma::matrix_b, 16, 16, 16, __half, wmma::row_major> bf[2];
            #pragma unroll
            for (int i = 0; i < 2; i++)
                wmma::load_matrix_sync(af[i], &KPs[(wr * 32 + i * 16) * 72 + kk], 72);
            #pragma unroll
            for (int jj = 0; jj < 2; jj++)
                wmma::load_matrix_sync(bf[jj], &Vs[kk * 72 + wc * 32 + jj * 16], 72);
            #pragma unroll
            for (int i = 0; i < 2; i++)
                #pragma unroll
                for (int jj = 0; jj < 2; jj++)
                    wmma::mma_sync(accy[i][jj], af[i], bf[jj], accy[i][jj]);
        }
        __syncthreads();
    }

    #pragma unroll
    for (int i = 0; i < 2; i++)
        #pragma unroll
        for (int jj = 0; jj < 2; jj++) {
            size_t off = ((size_t)(b * T_ + qglob0 + wr * 32 + i * 16)) * C_
                       + h * HD + wc * 32 + jj * 16;
            wmma::store_matrix_sync(&out[off], accy[i][jj], C_, wmma::mem_row_major);
        }
}

// ---------------------------------------------------------------------------
extern "C" void kernel_launch(void* const* d_in, const int* in_sizes, int n_in,
                              void* d_out, int out_size) {
    const void* x    = nullptr;
    const void* W    = nullptr;
    const void* bias = nullptr;
    for (int i = 0; i < n_in; i++) {
        if (in_sizes[i] == M_TOTAL * C_)      x    = d_in[i];
        else if (in_sizes[i] == C_ * N3C)     W    = d_in[i];
        else if (in_sizes[i] == N3C)          bias = d_in[i];
    }
    float* out = (float*)d_out;

    // 1) detect input dtype from x's value distribution
    probe_kernel<<<1, 256>>>(x);

    // 2) normalize all inputs to fp16 scratch
    __half* dx; cudaGetSymbolAddress((void**)&dx, g_x);
    __half* dW; cudaGetSymbolAddress((void**)&dW, g_W);
    __half* db; cudaGetSymbolAddress((void**)&db, g_b);
    conv_kernel<<<512, 256>>>(x,    dx, M_TOTAL * C_);
    conv_kernel<<<512, 256>>>(W,    dW, C_ * N3C);
    conv_kernel<<<4,   256>>>(bias, db, N3C);

    // 3) QKV projection
    dim3 g1(M_TOTAL / 64, N3C / 64);
    qkv_kernel<<<g1, 128>>>();

    // 4) causal ReLU attention
    dim3 g2(T_ / 64, H_, B_);
    attn_kernel<<<g2, 128>>>(out);
}

// round 5
// speedup vs baseline: 1.1534x; 1.1534x over previous
#include <cuda_runtime.h>
#include <cuda_fp16.h>
#include <cuda_bf16.h>
#include <mma.h>
#include <math.h>

using namespace nvcuda;

#define B_  2
#define T_  2048
#define C_  1024
#define H_  16
#define HD  64
#define M_TOTAL (B_ * T_)          // 4096
#define N3C (3 * C_)               // 3072
#define SLAB ((size_t)T_ * HD)

// fp16-normalized copies of the inputs
__device__ __half g_x[M_TOTAL * C_];
__device__ __half g_W[C_ * N3C];
__device__ __half g_b[N3C];
// q/k/v in [B][H][T][HD] fp16 layout
__device__ __half g_q[B_ * H_ * T_ * HD];
__device__ __half g_k[B_ * H_ * T_ * HD];
__device__ __half g_v[B_ * H_ * T_ * HD];
// detected input dtype: 0=fp16, 1=bf16, 2=fp32
__device__ int g_flag;

// ---------------------------------------------------------------------------
// cp.async helpers
// ---------------------------------------------------------------------------
__device__ __forceinline__ void cp_async16(void* dst, const void* src) {
    unsigned s = (unsigned)__cvta_generic_to_shared(dst);
    asm volatile("cp.async.cg.shared.global [%0], [%1], 16;\n" :: "r"(s), "l"(src));
}
#define CP_COMMIT() asm volatile("cp.async.commit_group;\n" ::: "memory")
#define CP_WAIT1()  asm volatile("cp.async.wait_group 1;\n" ::: "memory")
#define CP_WAIT0()  asm volatile("cp.async.wait_group 0;\n" ::: "memory")

// ---------------------------------------------------------------------------
// Probe: decide input dtype from x's value distribution (x~N(0,1), E|x|=.798)
// ---------------------------------------------------------------------------
__global__ void probe_kernel(const void* xraw) {
    __shared__ float s[3];
    const int tid = threadIdx.x;
    if (tid < 3) s[tid] = 0.0f;
    __syncthreads();
    const __half*        ph = (const __half*)xraw;
    const __nv_bfloat16* pb = (const __nv_bfloat16*)xraw;
    const float*         pf = (const float*)xraw;
    float a0 = 0.f, a1 = 0.f, a2 = 0.f;
    for (int i = tid; i < 4096; i += 256) {
        float v0 = fabsf(__half2float(ph[i]));
        float v1 = fabsf(__bfloat162float(pb[i]));
        float v2 = fabsf(pf[i]);
        if (!isfinite(v0) || v0 > 1e6f) v0 = 1e6f;
        if (!isfinite(v1) || v1 > 1e6f) v1 = 1e6f;
        if (!isfinite(v2) || v2 > 1e6f) v2 = 1e6f;
        a0 += v0; a1 += v1; a2 += v2;
    }
    atomicAdd(&s[0], a0); atomicAdd(&s[1], a1); atomicAdd(&s[2], a2);
    __syncthreads();
    if (tid == 0) {
        int best = 0; float bestd = 1e30f;
        #pragma unroll
        for (int j = 0; j < 3; j++) {
            float m = fmaxf(s[j] / 4096.0f, 1e-30f);
            float d = fabsf(logf(m / 0.798f));
            if (d < bestd) { bestd = d; best = j; }
        }
        g_flag = best;
    }
}

__global__ void conv_kernel(const void* __restrict__ src,
                            __half* __restrict__ dst, int n) {
    const int flag = g_flag;
    const int stride = gridDim.x * blockDim.x;
    for (int i = blockIdx.x * blockDim.x + threadIdx.x; i < n; i += stride) {
        float v;
        if (flag == 0)      v = __half2float(((const __half*)src)[i]);
        else if (flag == 1) v = __bfloat162float(((const __nv_bfloat16*)src)[i]);
        else                v = ((const float*)src)[i];
        dst[i] = __float2half(v);
    }
}

// ---------------------------------------------------------------------------
// Kernel 1: QKV = x @ W + b -> scatter into q/k/v [B][H][T][HD]
// 128x64 tile / block, 8 warps (4x2), BK=32 double-buffered cp.async.
// ---------------------------------------------------------------------------
#define QK_AS_STRIDE 40   // 32 + 8 halves pad (80B rows, 16B-mult)
#define QK_BS_STRIDE 72   // 64 + 8
#define QK_AS_STAGE  (128 * QK_AS_STRIDE)          // halves
#define QK_BS_STAGE  (32 * QK_BS_STRIDE)

__global__ __launch_bounds__(256, 1) void qkv_kernel() {
    __shared__ __align__(16) char smemraw[36864];  // union: As+Bs | Cs
    __half* As = (__half*)smemraw;                              // 2 stages, 20480 B
    __half* Bs = (__half*)(smemraw + 2 * QK_AS_STAGE * 2);      // 2 stages,  9216 B
    float*  Cs = (float*)smemraw;                               // epilogue, 36864 B

    const int tm  = blockIdx.x;   // 0..31 (128 rows each)
    const int tn  = blockIdx.y;   // 0..47 (64 cols each)
    const int tid = threadIdx.x;
    const int warp = tid >> 5;
    const int wr = warp >> 1, wc = warp & 1;   // 4x2

    auto prefetch = [&](int ki, int stage) {
        const int k0 = ki * 32;
        __half* as = As + stage * QK_AS_STAGE;
        __half* bs = Bs + stage * QK_BS_STAGE;
        #pragma unroll
        for (int v = tid; v < 512; v += 256) {            // A: 128x32
            int r = v >> 2, c8 = (v & 3) << 3;
            cp_async16(&as[r * QK_AS_STRIDE + c8],
                       &g_x[(size_t)(tm * 128 + r) * C_ + k0 + c8]);
        }
        {                                                  // B: 32x64
            int r = tid >> 3, c8 = (tid & 7) << 3;
            cp_async16(&bs[r * QK_BS_STRIDE + c8],
                       &g_W[(size_t)(k0 + r) * N3C + tn * 64 + c8]);
        }
    };

    wmma::fragment<wmma::accumulator, 16, 16, 16, float> acc[2][2];
    #pragma unroll
    for (int i = 0; i < 2; i++)
        #pragma unroll
        for (int j = 0; j < 2; j++)
            wmma::fill_fragment(acc[i][j], 0.0f);

    prefetch(0, 0);
    CP_COMMIT();

    for (int ki = 0; ki < 32; ki++) {
        const int cur = ki & 1;
        __syncthreads();                      // prior-iter reads of stage !cur done
        if (ki < 31) { prefetch(ki + 1, cur ^ 1); CP_COMMIT(); CP_WAIT1(); }
        else         { CP_WAIT0(); }
        __syncthreads();                      // stage cur ready

        const __half* as = As + cur * QK_AS_STAGE;
        const __half* bs = Bs + cur * QK_BS_STAGE;
        #pragma unroll
        for (int kk = 0; kk < 32; kk += 16) {
            wmma::fragment<wmma::matrix_a, 16, 16, 16, __half, wmma::row_major> af[2];
            wmma::fragment<wmma::matrix_b, 16, 16, 16, __half, wmma::row_major> bf[2];
            #pragma unroll
            for (int i = 0; i < 2; i++)
                wmma::load_matrix_sync(af[i], &as[(wr * 32 + i * 16) * QK_AS_STRIDE + kk], QK_AS_STRIDE);
            #pragma unroll
            for (int j = 0; j < 2; j++)
                wmma::load_matrix_sync(bf[j], &bs[kk * QK_BS_STRIDE + wc * 32 + j * 16], QK_BS_STRIDE);
            #pragma unroll
            for (int i = 0; i < 2; i++)
                #pragma unroll
                for (int j = 0; j < 2; j++)
                    wmma::mma_sync(acc[i][j], af[i], bf[j], acc[i][j]);
        }
    }
    __syncthreads();  // done reading As/Bs; Cs aliases them

    #pragma unroll
    for (int i = 0; i < 2; i++)
        #pragma unroll
        for (int j = 0; j < 2; j++)
            wmma::store_matrix_sync(&Cs[(wr * 32 + i * 16) * 72 + wc * 32 + j * 16],
                                    acc[i][j], 72, wmma::mem_row_major);
    __syncthreads();

    const int third = tn >> 4;          // 0=q 1=k 2=v
    const int h     = tn & 15;
    __half* dst = (third == 0) ? g_q : (third == 1) ? g_k : g_v;

    #pragma unroll
    for (int e = tid; e < 8192; e += 256) {
        int r = e >> 6, c = e & 63;
        int row = tm * 128 + r;
        int b = row >> 11;
        int t = row & 2047;
        float val = Cs[r * 72 + c] + __half2float(g_b[tn * 64 + c]);
        dst[(((size_t)(b * H_ + h)) * T_ + t) * HD + c] = __float2half(val);
    }
}

// ---------------------------------------------------------------------------
// Kernel 2: causal ReLU attention.
// 128-row Q tile / block, 8 warps (4x2). K/V 64-row tiles double-buffered
// via cp.async. Dynamic smem (110.6 KB).
// ---------------------------------------------------------------------------
#define AT_OFF_Q 0
#define AT_OFF_K 18432
#define AT_OFF_V 36864
#define AT_OFF_S 55296
#define AT_OFF_P 92160
#define AT_SMEM  110592
#define AT_KV_STAGE (64 * 72)   // halves

__global__ __launch_bounds__(256, 1) void attn_kernel(float* __restrict__ out) {
    extern __shared__ __align__(16) char dsm[];
    __half* Qs = (__half*)(dsm + AT_OFF_Q);   // 128x72
    __half* Ks = (__half*)(dsm + AT_OFF_K);   // 2 x 64x72
    __half* Vs = (__half*)(dsm + AT_OFF_V);   // 2 x 64x72
    float*  Ss = (float*) (dsm + AT_OFF_S);   // 128x72
    __half* Ps = (__half*)(dsm + AT_OFF_P);   // 128x72

    const int qi = (gridDim.x - 1) - blockIdx.x;   // heavy tiles first
    const int h  = blockIdx.y;
    const int b  = blockIdx.z;
    const int tid = threadIdx.x;
    const int warp = tid >> 5;
    const int wr = warp >> 1, wc = warp & 1;       // 4x2

    const size_t slab = ((size_t)(b * H_ + h)) * SLAB;
    const __half* qbase = g_q + slab + (size_t)qi * 128 * HD;
    const __half* kbase = g_k + slab;
    const __half* vbase = g_v + slab;

    auto prefetch_kv = [&](int j, int stage) {
        __half* ks = Ks + stage * AT_KV_STAGE;
        __half* vs = Vs + stage * AT_KV_STAGE;
        #pragma unroll
        for (int v = tid; v < 1024; v += 256) {
            int vv = v & 511;
            int r = vv >> 3, c8 = (vv & 7) << 3;
            const __half* src = (v < 512)
                ? &kbase[(size_t)(j * 64 + r) * HD + c8]
                : &vbase[(size_t)(j * 64 + r) * HD + c8];
            __half* dst = (v < 512) ? &ks[r * 72 + c8] : &vs[r * 72 + c8];
            cp_async16(dst, src);
        }
    };

    // group 0: Q tile + K/V tile 0
    #pragma unroll
    for (int v = tid; v < 1024; v += 256) {
        int r = v >> 3, c8 = (v & 7) << 3;
        cp_async16(&Qs[r * 72 + c8], &qbase[(size_t)r * HD + c8]);
    }
    prefetch_kv(0, 0);
    CP_COMMIT();

    wmma::fragment<wmma::accumulator, 16, 16, 16, float> accy[2][2];
    #pragma unroll
    for (int i = 0; i < 2; i++)
        #pragma unroll
        for (int j = 0; j < 2; j++)
            wmma::fill_fragment(accy[i][j], 0.0f);

    const int qglob0 = qi * 128;
    const int jmax = 2 * qi + 1;

    for (int j = 0; j <= jmax; j++) {
        const int cur = j & 1;
        __syncthreads();                 // all reads of stage !cur (iter j-1) + Ps done
        if (j < jmax) { prefetch_kv(j + 1, cur ^ 1); CP_COMMIT(); CP_WAIT1(); }
        else          { CP_WAIT0(); }
        __syncthreads();                 // stage cur (and Q on j=0) ready

        const __half* ks = Ks + cur * AT_KV_STAGE;
        const __half* vs = Vs + cur * AT_KV_STAGE;

        // S = Q @ K^T
        wmma::fragment<wmma::accumulator, 16, 16, 16, float> accs[2][2];
        #pragma unroll
        for (int i = 0; i < 2; i++)
            #pragma unroll
            for (int jj = 0; jj < 2; jj++)
                wmma::fill_fragment(accs[i][jj], 0.0f);

        #pragma unroll
        for (int kk = 0; kk < 64; kk += 16) {
            wmma::fragment<wmma::matrix_a, 16, 16, 16, __half, wmma::row_major> af[2];
            wmma::fragment<wmma::matrix_b, 16, 16, 16, __half, wmma::col_major> bf[2];
            #pragma unroll
            for (int i = 0; i < 2; i++)
                wmma::load_matrix_sync(af[i], &Qs[(wr * 32 + i * 16) * 72 + kk], 72);
            #pragma unroll
            for (int jj = 0; jj < 2; jj++)
                wmma::load_matrix_sync(bf[jj], &ks[(wc * 32 + jj * 16) * 72 + kk], 72);
            #pragma unroll
            for (int i = 0; i < 2; i++)
                #pragma unroll
                for (int jj = 0; jj < 2; jj++)
                    wmma::mma_sync(accs[i][jj], af[i], bf[jj], accs[i][jj]);
        }
        #pragma unroll
        for (int i = 0; i < 2; i++)
            #pragma unroll
            for (int jj = 0; jj < 2; jj++)
                wmma::store_matrix_sync(&Ss[(wr * 32 + i * 16) * 72 + wc * 32 + jj * 16],
                                        accs[i][jj], 72, wmma::mem_row_major);
        __syncthreads();

        // scale + relu + causal mask -> fp16 P (half2 vectorized)
        const int kglob0 = j * 64;
        #pragma unroll
        for (int e = tid; e < 4096; e += 256) {
            int r = e >> 5, c = (e & 31) << 1;
            float s0 = Ss[r * 72 + c]     * 0.125f;
            float s1 = Ss[r * 72 + c + 1] * 0.125f;
            int qpos = qglob0 + r, kpos = kglob0 + c;
            s0 = (kpos     <= qpos) ? fmaxf(s0, 0.f) : 0.f;
            s1 = (kpos + 1 <= qpos) ? fmaxf(s1, 0.f) : 0.f;
            *(half2*)&Ps[r * 72 + c] = __floats2half2_rn(s0, s1);
        }
        __syncthreads();

        // Y += P @ V
        #pragma unroll
        for (int kk = 0; kk < 64; kk += 16) {
            wmma::fragment<wmma::matrix_a, 16, 16, 16, __half, wmma::row_major> af[2];
            wmma::fragment<wmma::matrix_b, 16, 16, 16, __half, wmma::row_major> bf[2];
            #pragma unroll
            for (int i = 0; i < 2; i++)
                wmma::load_matrix_sync(af[i], &Ps[(wr * 32 + i * 16) * 72 + kk], 72);
            #pragma unroll
            for (int jj = 0; jj < 2; jj++)
                wmma::load_matrix_sync(bf[jj], &vs[kk * 72 + wc * 32 + jj * 16], 72);
            #pragma unroll
            for (int i = 0; i < 2; i++)
                #pragma unroll
                for (int jj = 0; jj < 2; jj++)
                    wmma::mma_sync(accy[i][jj], af[i], bf[jj], accy[i][jj]);
        }
    }

    // Y (fp32) straight to out[b][t][h*64+d]
    #pragma unroll
    for (int i = 0; i < 2; i++)
        #pragma unroll
        for (int jj = 0; jj < 2; jj++) {
            size_t off = ((size_t)(b * T_ + qglob0 + wr * 32 + i * 16)) * C_
                       + h * HD + wc * 32 + jj * 16;
            wmma::store_matrix_sync(&out[off], accy[i][jj], C_, wmma::mem_row_major);
        }
}

// ---------------------------------------------------------------------------
extern "C" void kernel_launch(void* const* d_in, const int* in_sizes, int n_in,
                              void* d_out, int out_size) {
    const void* x    = nullptr;
    const void* W    = nullptr;
    const void* bias = nullptr;
    for (int i = 0; i < n_in; i++) {
        if (in_sizes[i] == M_TOTAL * C_)      x    = d_in[i];
        else if (in_sizes[i] == C_ * N3C)     W    = d_in[i];
        else if (in_sizes[i] == N3C)          bias = d_in[i];
    }
    float* out = (float*)d_out;

    probe_kernel<<<1, 256>>>(x);

    __half* dx; cudaGetSymbolAddress((void**)&dx, g_x);
    __half* dW; cudaGetSymbolAddress((void**)&dW, g_W);
    __half* db; cudaGetSymbolAddress((void**)&db, g_b);
    conv_kernel<<<512, 256>>>(x,    dx, M_TOTAL * C_);
    conv_kernel<<<512, 256>>>(W,    dW, C_ * N3C);
    conv_kernel<<<4,   256>>>(bias, db, N3C);

    dim3 g1(M_TOTAL / 128, N3C / 64);              // (32, 48)
    qkv_kernel<<<g1, 256>>>();

    cudaFuncSetAttribute(attn_kernel,
                         cudaFuncAttributeMaxDynamicSharedMemorySize, AT_SMEM);
    dim3 g2(T_ / 128, H_, B_);                     // (16, 16, 2)
    attn_kernel<<<g2, 256, AT_SMEM>>>(out);
}

// round 13
// speedup vs baseline: 1.5132x; 1.3120x over previous
#include <cuda_runtime.h>
#include <cuda_fp16.h>
#include <cuda_bf16.h>
#include <math.h>
#include <stdint.h>

#define B_  2
#define T_  2048
#define C_  1024
#define H_  16
#define HD  64
#define M_TOTAL 4096
#define N3C 3072
#define SLAB ((size_t)T_ * HD)

__device__ __half g_x[M_TOTAL * C_];
__device__ __half g_W[C_ * N3C];
__device__ __half g_b[N3C];
__device__ __half g_q[B_ * H_ * T_ * HD];
__device__ __half g_k[B_ * H_ * T_ * HD];
__device__ __half g_v[B_ * H_ * T_ * HD];
__device__ int g_flag;

// ---------------------------------------------------------------------------
// helpers
// ---------------------------------------------------------------------------
__device__ __forceinline__ uint32_t smem_u32(const void* p) {
    uint32_t a;
    asm("{ .reg .u64 t; cvta.to.shared.u64 t, %1; cvt.u32.u64 %0, t; }" : "=r"(a) : "l"(p));
    return a;
}
__device__ __forceinline__ void cp_async16(void* dst, const void* src) {
    unsigned s = (unsigned)__cvta_generic_to_shared(dst);
    asm volatile("cp.async.cg.shared.global [%0], [%1], 16;\n" :: "r"(s), "l"(src));
}
#define CP_COMMIT() asm volatile("cp.async.commit_group;\n" ::: "memory")
#define CP_WAIT0()  asm volatile("cp.async.wait_group 0;\n" ::: "memory")

__device__ __forceinline__ void ldsm4(uint32_t* r, uint32_t addr) {
    asm volatile("ldmatrix.sync.aligned.m8n8.x4.shared.b16 {%0,%1,%2,%3}, [%4];"
        : "=r"(r[0]), "=r"(r[1]), "=r"(r[2]), "=r"(r[3]) : "r"(addr));
}
__device__ __forceinline__ void ldsm4t(uint32_t* r, uint32_t addr) {
    asm volatile("ldmatrix.sync.aligned.m8n8.x4.trans.shared.b16 {%0,%1,%2,%3}, [%4];"
        : "=r"(r[0]), "=r"(r[1]), "=r"(r[2]), "=r"(r[3]) : "r"(addr));
}
// D = A*B + D : m16n8k16 row.col f32 accum
__device__ __forceinline__ void mma16816(float* c, const uint32_t* a, const uint32_t* b) {
    asm volatile("mma.sync.aligned.m16n8k16.row.col.f32.f16.f16.f32 "
        "{%0,%1,%2,%3}, {%4,%5,%6,%7}, {%8,%9}, {%0,%1,%2,%3};"
        : "+f"(c[0]), "+f"(c[1]), "+f"(c[2]), "+f"(c[3])
        : "r"(a[0]), "r"(a[1]), "r"(a[2]), "r"(a[3]), "r"(b[0]), "r"(b[1]));
}

// ---------------------------------------------------------------------------
// dtype probe + conversion (proven in R3)
// ---------------------------------------------------------------------------
__global__ void probe_kernel(const void* xraw) {
    __shared__ float s[3];
    const int tid = threadIdx.x;
    if (tid < 3) s[tid] = 0.0f;
    __syncthreads();
    const __half*        ph = (const __half*)xraw;
    const __nv_bfloat16* pb = (const __nv_bfloat16*)xraw;
    const float*         pf = (const float*)xraw;
    float a0 = 0.f, a1 = 0.f, a2 = 0.f;
    for (int i = tid; i < 4096; i += 256) {
        float v0 = fabsf(__half2float(ph[i]));
        float v1 = fabsf(__bfloat162float(pb[i]));
        float v2 = fabsf(pf[i]);
        if (!isfinite(v0) || v0 > 1e6f) v0 = 1e6f;
        if (!isfinite(v1) || v1 > 1e6f) v1 = 1e6f;
        if (!isfinite(v2) || v2 > 1e6f) v2 = 1e6f;
        a0 += v0; a1 += v1; a2 += v2;
    }
    atomicAdd(&s[0], a0); atomicAdd(&s[1], a1); atomicAdd(&s[2], a2);
    __syncthreads();
    if (tid == 0) {
        int best = 0; float bestd = 1e30f;
        #pragma unroll
        for (int j = 0; j < 3; j++) {
            float m = fmaxf(s[j] / 4096.0f, 1e-30f);
            float d = fabsf(logf(m / 0.798f));
            if (d < bestd) { bestd = d; best = j; }
        }
        g_flag = best;
    }
}

__global__ void conv_kernel(const void* __restrict__ src,
                            __half* __restrict__ dst, int n) {
    const int flag = g_flag;
    const int stride = gridDim.x * blockDim.x;
    for (int i = blockIdx.x * blockDim.x + threadIdx.x; i < n; i += stride) {
        float v;
        if (flag == 0)      v = __half2float(((const __half*)src)[i]);
        else if (flag == 1) v = __bfloat162float(((const __nv_bfloat16*)src)[i]);
        else                v = ((const float*)src)[i];
        dst[i] = __float2half(v);
    }
}

// ---------------------------------------------------------------------------
// Kernel 1: QKV GEMM. 128x128 tile/CTA, 8 warps (2x4 -> 64x32 each), BK=32
// double-buffered cp.async, raw mma, fragment-direct epilogue (+bias).
// ---------------------------------------------------------------------------
#define QA_STRIDE 40    // halves (80 B rows)
#define QB_STRIDE 136   // halves (272 B rows)
#define QA_BYTES  (128 * QA_STRIDE * 2)   // 10240 per stage
#define QB_BYTES  (32 * QB_STRIDE * 2)    //  8704 per stage
#define QO_A(s)   ((s) * QA_BYTES)
#define QO_B(s)   (2 * QA_BYTES + (s) * QB_BYTES)
#define Q_SMEM    (2 * QA_BYTES + 2 * QB_BYTES)   // 37888

__global__ __launch_bounds__(256, 2) void qkv_kernel() {
    extern __shared__ __align__(16) char dsm[];
    const uint32_t sb = smem_u32(dsm);
    const int tid = threadIdx.x, warp = tid >> 5, L = tid & 31;
    const int tm = blockIdx.x;               // 0..31
    const int tn = blockIdx.y;               // 0..23
    const int wr = warp >> 2, wc = warp & 3; // 2x4 : 64x32 warp tile
    const int g = L >> 2, tq = L & 3;        // mma group / quad

    const int aRow = (L & 7) + (L & 8);      // A/trans-B ldmatrix row pattern
    const int aC8  = (L & 16) >> 1;          // col +8 for upper half

    auto prefetch = [&](int i, int s) {
        const int k0 = i * 32;
        char* as = dsm + QO_A(s);
        char* bs = dsm + QO_B(s);
        #pragma unroll
        for (int v = tid; v < 512; v += 256) {   // A: 128x32 halves
            int r = v >> 2, c16 = v & 3;
            cp_async16(as + (r * QA_STRIDE + c16 * 8) * 2,
                       &g_x[(size_t)(tm * 128 + r) * C_ + k0 + c16 * 8]);
        }
        #pragma unroll
        for (int v = tid; v < 512; v += 256) {   // B: 32x128 halves
            int r = v >> 4, c16 = v & 15;
            cp_async16(bs + (r * QB_STRIDE + c16 * 8) * 2,
                       &g_W[(size_t)(k0 + r) * N3C + tn * 128 + c16 * 8]);
        }
    };

    float acc[4][4][4];
    #pragma unroll
    for (int i = 0; i < 4; i++)
        #pragma unroll
        for (int j = 0; j < 4; j++)
            #pragma unroll
            for (int e = 0; e < 4; e++) acc[i][j][e] = 0.0f;

    prefetch(0, 0); CP_COMMIT();

    for (int i = 0; i < 32; i++) {
        const int s = i & 1;
        CP_WAIT0();
        __syncthreads();
        if (i < 31) { prefetch(i + 1, s ^ 1); CP_COMMIT(); }

        const uint32_t sa = sb + QO_A(s);
        const uint32_t sbb = sb + QO_B(s);
        #pragma unroll
        for (int u = 0; u < 2; u++) {       // ksteps of 16
            uint32_t a[4][4];
            #pragma unroll
            for (int mi = 0; mi < 4; mi++) {
                int row = wr * 64 + mi * 16 + aRow;
                int col = u * 16 + aC8;
                ldsm4(a[mi], sa + (row * QA_STRIDE + col) * 2);
            }
            #pragma unroll
            for (int np = 0; np < 2; np++) { // n-tile pairs (16 cols)
                uint32_t b[4];
                int row = u * 16 + aRow;                   // W k-rows
                int col = wc * 32 + np * 16 + aC8;
                ldsm4t(b, sbb + (row * QB_STRIDE + col) * 2);
                #pragma unroll
                for (int mi = 0; mi < 4; mi++) {
                    mma16816(acc[mi][2 * np],     a[mi], b);
                    mma16816(acc[mi][2 * np + 1], a[mi], b + 2);
                }
            }
        }
    }

    // epilogue: fragments -> +bias -> fp16 -> q/k/v scatter
    const int third = tn >> 3;
    __half* base = (third == 0) ? g_q : (third == 1) ? g_k : g_v;
    #pragma unroll
    for (int mi = 0; mi < 4; mi++) {
        #pragma unroll
        for (int rr = 0; rr < 2; rr++) {
            int row = tm * 128 + wr * 64 + mi * 16 + g + rr * 8;
            int b = row >> 11, t = row & 2047;
            #pragma unroll
            for (int ni = 0; ni < 4; ni++) {
                int cl = wc * 32 + ni * 8 + 2 * tq;    // col in 128-tile, even
                int h = (tn & 7) * 2 + (cl >> 6);
                int c = cl & 63;
                half2 bias = *(const half2*)&g_b[tn * 128 + cl];
                float v0 = acc[mi][ni][rr * 2]     + __half2float(__low2half(bias));
                float v1 = acc[mi][ni][rr * 2 + 1] + __half2float(__high2half(bias));
                *(half2*)&base[(((size_t)(b * H_ + h)) * T_ + t) * HD + c] =
                    __floats2half2_rn(v0, v1);
            }
        }
    }
}

// ---------------------------------------------------------------------------
// Kernel 2: causal ReLU attention, FA2-style register-resident.
// CTA = 128 q-rows, 8 warps (16 rows each). K/V 64-row tiles double-buffered.
// S accum (f32 frags) -> scale+relu+mask in regs -> P a-frags -> Y += P V.
// One __syncthreads per k-tile.
// ---------------------------------------------------------------------------
#define AT_STRIDE 72                       // halves (144 B rows)
#define AQ_BYTES  (128 * AT_STRIDE * 2)    // 18432
#define AKV_BYTES (64 * AT_STRIDE * 2)     //  9216 per tensor per stage
#define AO_Q      0
#define AO_K(s)   (AQ_BYTES + (s) * AKV_BYTES)
#define AO_V(s)   (AQ_BYTES + 2 * AKV_BYTES + (s) * AKV_BYTES)
#define A_SMEM    (AQ_BYTES + 4 * AKV_BYTES)   // 55296

__global__ __launch_bounds__(256, 2) void attn_kernel(float* __restrict__ out) {
    extern __shared__ __align__(16) char dsm[];
    const uint32_t sb = smem_u32(dsm);
    const int tid = threadIdx.x, warp = tid >> 5, L = tid & 31;
    const int qi = (gridDim.x - 1) - blockIdx.x;    // heavy tiles first
    const int h  = blockIdx.y;
    const int b  = blockIdx.z;
    const int g = L >> 2, tq = L & 3;

    const int aRow = (L & 7) + (L & 8);      // A/V ldmatrix pattern
    const int aC8  = (L & 16) >> 1;
    const int kRow = (L & 7) + ((L & 16) >> 1);  // K (B-op) pattern
    const int kC8  = L & 8;

    const size_t slab = ((size_t)(b * H_ + h)) * SLAB;
    const __half* qbase = g_q + slab + (size_t)qi * 128 * HD;
    const __half* kbase = g_k + slab;
    const __half* vbase = g_v + slab;

    auto prefetch_kv = [&](int j, int s) {
        char* ks = dsm + AO_K(s);
        char* vs = dsm + AO_V(s);
        #pragma unroll
        for (int v = tid; v < 1024; v += 256) {
            int vv = v & 511;
            int r = vv >> 3, c16 = vv & 7;
            const __half* src = (v < 512)
                ? &kbase[(size_t)(j * 64 + r) * HD + c16 * 8]
                : &vbase[(size_t)(j * 64 + r) * HD + c16 * 8];
            char* dst = ((v < 512) ? ks : vs) + (r * AT_STRIDE + c16 * 8) * 2;
            cp_async16(dst, src);
        }
    };

    // prologue: Q + K/V(0)
    #pragma unroll
    for (int v = tid; v < 1024; v += 256) {
        int r = v >> 3, c16 = v & 7;
        cp_async16(dsm + AO_Q + (r * AT_STRIDE + c16 * 8) * 2,
                   &qbase[(size_t)r * HD + c16 * 8]);
    }
    prefetch_kv(0, 0);
    CP_COMMIT();
    CP_WAIT0();
    __syncthreads();

    // Q -> registers (resident): 16 rows x 64 cols = 4 ksteps x 4 regs
    uint32_t qa[4][4];
    #pragma unroll
    for (int u = 0; u < 4; u++) {
        int row = warp * 16 + aRow;
        int col = u * 16 + aC8;
        ldsm4(qa[u], sb + AO_Q + (row * AT_STRIDE + col) * 2);
    }

    float ya[8][4];
    #pragma unroll
    for (int v = 0; v < 8; v++)
        #pragma unroll
        for (int e = 0; e < 4; e++) ya[v][e] = 0.0f;

    const int qglob0 = qi * 128;
    const int row0 = qglob0 + warp * 16 + g;   // this thread's S rows: row0, row0+8
    const int jmax = 2 * qi + 1;

    for (int j = 0; j <= jmax; j++) {
        const int s = j & 1;
        if (j > 0) { CP_WAIT0(); __syncthreads(); }
        if (j < jmax) { prefetch_kv(j + 1, s ^ 1); CP_COMMIT(); }

        // ---- S = Q K^T  (f32 frags, 8 n-tiles of 8 key-cols) ----
        float sc[8][4];
        #pragma unroll
        for (int v = 0; v < 8; v++)
            #pragma unroll
            for (int e = 0; e < 4; e++) sc[v][e] = 0.0f;

        const uint32_t ks = sb + AO_K(s);
        #pragma unroll
        for (int u = 0; u < 4; u++) {            // kstep over d
            #pragma unroll
            for (int np = 0; np < 4; np++) {     // key-tile pairs (16 keys)
                uint32_t kb[4];
                int row = np * 16 + kRow;        // K t-rows
                int col = u * 16 + kC8;          // d
                ldsm4(kb, ks + (row * AT_STRIDE + col) * 2);
                mma16816(sc[2 * np],     qa[u], kb);
                mma16816(sc[2 * np + 1], qa[u], kb + 2);
            }
        }

        // ---- scale + relu + causal mask in regs; pack P a-frags ----
        const int kg = j * 64 + 2 * tq;
        uint32_t pa[4][4];
        #pragma unroll
        for (int v = 0; v < 8; v++) {
            int c0 = kg + v * 8, c1 = c0 + 1;
            float e0 = (c0 <= row0)     ? fmaxf(sc[v][0] * 0.125f, 0.f) : 0.f;
            float e1 = (c1 <= row0)     ? fmaxf(sc[v][1] * 0.125f, 0.f) : 0.f;
            float e2 = (c0 <= row0 + 8) ? fmaxf(sc[v][2] * 0.125f, 0.f) : 0.f;
            float e3 = (c1 <= row0 + 8) ? fmaxf(sc[v][3] * 0.125f, 0.f) : 0.f;
            half2 lo = __floats2half2_rn(e0, e1);
            half2 hi = __floats2half2_rn(e2, e3);
            pa[v >> 1][(v & 1) * 2]     = *(uint32_t*)&lo;
            pa[v >> 1][(v & 1) * 2 + 1] = *(uint32_t*)&hi;
        }

        // ---- Y += P V  (np 0..3 covers the FULL d=64; R10 bug was np<2) ----
        const uint32_t vs = sb + AO_V(s);
        #pragma unroll
        for (int u = 0; u < 4; u++) {            // kstep over t
            #pragma unroll
            for (int np = 0; np < 4; np++) {     // d-tile pairs (16 cols)
                uint32_t vb[4];
                int row = u * 16 + aRow;         // V t-rows
                int col = np * 16 + aC8;         // d
                ldsm4t(vb, vs + (row * AT_STRIDE + col) * 2);
                mma16816(ya[2 * np],     pa[u], vb);
                mma16816(ya[2 * np + 1], pa[u], vb + 2);
            }
        }
    }

    // epilogue: Y (f32) -> out[b][t][h*64+d]
    #pragma unroll
    for (int rr = 0; rr < 2; rr++) {
        int row = qglob0 + warp * 16 + g + rr * 8;
        float* dst = out + ((size_t)(b * T_ + row)) * C_ + h * HD;
        #pragma unroll
        for (int v = 0; v < 8; v++) {
            int d = v * 8 + 2 * tq;
            *(float2*)&dst[d] = make_float2(ya[v][rr * 2], ya[v][rr * 2 + 1]);
        }
    }
}

// ---------------------------------------------------------------------------
extern "C" void kernel_launch(void* const* d_in, const int* in_sizes, int n_in,
                              void* d_out, int out_size) {
    const void* x    = nullptr;
    const void* W    = nullptr;
    const void* bias = nullptr;
    for (int i = 0; i < n_in; i++) {
        if (in_sizes[i] == M_TOTAL * C_)      x    = d_in[i];
        else if (in_sizes[i] == C_ * N3C)     W    = d_in[i];
        else if (in_sizes[i] == N3C)          bias = d_in[i];
    }
    float* out = (float*)d_out;

    probe_kernel<<<1, 256>>>(x);

    __half* dx; cudaGetSymbolAddress((void**)&dx, g_x);
    __half* dW; cudaGetSymbolAddress((void**)&dW, g_W);
    __half* db; cudaGetSymbolAddress((void**)&db, g_b);
    conv_kernel<<<512, 256>>>(x,    dx, M_TOTAL * C_);
    conv_kernel<<<512, 256>>>(W,    dW, C_ * N3C);
    conv_kernel<<<4,   256>>>(bias, db, N3C);

    cudaFuncSetAttribute(qkv_kernel,
                         cudaFuncAttributeMaxDynamicSharedMemorySize, Q_SMEM);
    dim3 g1(M_TOTAL / 128, N3C / 128);             // (32, 24)
    qkv_kernel<<<g1, 256, Q_SMEM>>>();

    cudaFuncSetAttribute(attn_kernel,
                         cudaFuncAttributeMaxDynamicSharedMemorySize, A_SMEM);
    dim3 g2(T_ / 128, H_, B_);                     // (16, 16, 2)
    attn_kernel<<<g2, 256, A_SMEM>>>(out);
}